// round 16
// baseline (speedup 1.0000x reference)
#include <cuda_runtime.h>
#include <cuda_bf16.h>

// Sparsemax over rows: x, mask are [8192, 4096] fp32; out fp32 same shape.
// z = (mask ? x : NEG_BIG) * 2 ; tau solves sum(relu(z - tau)) = 1 ;
// out = relu(z - tau)  (mask multiply implied: masked z is hugely negative).
//
// R16 = R15 (ballot gather into per-warp 8-slot segments, 2 barriers, slim
// warp-local Newton with ballot counts) + Newton's FIRST evaluation seeded
// through the existing gather barrier: each warp's partial sum(cand - T0)
// and count ride along in shared, so iteration 0 costs zero reductions.

#define ROWS 8192
#define COLS 4096
#define THREADS 256
#define NWARPS (THREADS / 32)
#define ELEMS (COLS / THREADS)   // 16 floats per thread
#define VEC (ELEMS / 4)          // 4 float4 per thread
#define WCAP 8                   // candidate slots per warp
#define CAP (NWARPS * WCAP)      // 64 total (2 per lane)

__global__ __launch_bounds__(THREADS, 5)
void sparsemax_kernel(const float* __restrict__ x,
                      const float* __restrict__ m,
                      float* __restrict__ out) {
    const int row = blockIdx.x;
    const int t   = threadIdx.x;
    const int lane = t & 31;
    const int wid  = t >> 5;

    const float4* __restrict__ xr = reinterpret_cast<const float4*>(x + (size_t)row * COLS);
    const float4* __restrict__ mr = reinterpret_cast<const float4*>(m + (size_t)row * COLS);
    float4* __restrict__ orow     = reinterpret_cast<float4*>(out + (size_t)row * COLS);

    __shared__ float shmax[NWARPS];
    __shared__ int   wovf[NWARPS];    // warp overflow flags
    __shared__ float cand[CAP];
    __shared__ float fs[2][NWARPS];   // seed sums / fallback double-buffer
    __shared__ int   fc[2][NWARPS];   // seed counts / fallback double-buffer

    // ---- Front-batch ALL loads (8 x LDG.128 in flight per thread) ----
    float4 xv[VEC];
    float4 mv[VEC];
#pragma unroll
    for (int v = 0; v < VEC; v++) xv[v] = xr[t + v * THREADS];
#pragma unroll
    for (int v = 0; v < VEC; v++) mv[v] = mr[t + v * THREADS];

    // Pre-initialize this warp's candidate segment (ordered by barrier 1).
    if (lane < WCAP) cand[wid * WCAP + lane] = -3.0e38f;

    // ---- Apply mask + temperature, track local max ----
    float z[ELEMS];
    float vmax = -3.0e38f;
    const float NEGZ = -9999999.9f * 2.0f;  // masked value after temperature
#pragma unroll
    for (int v = 0; v < VEC; v++) {
        float z0 = (mv[v].x != 0.0f) ? (xv[v].x * 2.0f) : NEGZ;
        float z1 = (mv[v].y != 0.0f) ? (xv[v].y * 2.0f) : NEGZ;
        float z2 = (mv[v].z != 0.0f) ? (xv[v].z * 2.0f) : NEGZ;
        float z3 = (mv[v].w != 0.0f) ? (xv[v].w * 2.0f) : NEGZ;
        z[v * 4 + 0] = z0;
        z[v * 4 + 1] = z1;
        z[v * 4 + 2] = z2;
        z[v * 4 + 3] = z3;
        vmax = fmaxf(vmax, fmaxf(fmaxf(z0, z1), fmaxf(z2, z3)));
    }

    // ---- Block max reduction ----
#pragma unroll
    for (int o = 16; o > 0; o >>= 1)
        vmax = fmaxf(vmax, __shfl_xor_sync(0xFFFFFFFFu, vmax, o));
    if (lane == 0) shmax[wid] = vmax;
    __syncthreads();                       // barrier 1
    float zmax = -3.0e38f;
#pragma unroll
    for (int i = 0; i < NWARPS; i++) zmax = fmaxf(zmax, shmax[i]);

    const float T0 = zmax - 1.0f;

    // ---- Ballot gather into this warp's private segment + seed partials ----
    int   lc = 0;
    float cv = -3.0e38f;
#pragma unroll
    for (int e = 0; e < ELEMS; e++) {
        if (z[e] > T0) { lc++; cv = z[e]; }
    }
    const unsigned has   = __ballot_sync(0xFFFFFFFFu, lc > 0);
    const unsigned multi = __ballot_sync(0xFFFFFFFFu, lc > 1);
    if (lc == 1) {
        int slot = __popc(has & ((1u << lane) - 1u));
        if (slot < WCAP) cand[wid * WCAP + slot] = cv;
    }
    // Warp partial for Newton's first evaluation at T0 (rides barrier 2).
    float part = (lc == 1) ? (cv - T0) : 0.0f;
#pragma unroll
    for (int o = 16; o > 0; o >>= 1)
        part += __shfl_xor_sync(0xFFFFFFFFu, part, o);
    if (lane == 0) {
        fs[0][wid]  = part;
        fc[0][wid]  = __popc(has);
        wovf[wid]   = (multi != 0u || __popc(has) > WCAP) ? 1 : 0;
    }
    __syncthreads();                       // barrier 2 (last barrier)

    bool ovf = false;
    float S0 = 0.0f;
    int   C0 = 0;
#pragma unroll
    for (int i = 0; i < NWARPS; i++) {
        ovf |= (wovf[i] != 0);
        S0  += fs[0][i];
        C0  += fc[0][i];
    }

    float tau;
    if (!ovf) {
        // ---- Slim warp-local Newton; iteration 0 comes from the seed ----
        float c0 = cand[lane +  0];
        float c1 = cand[lane + 32];

        float T = T0 + __fdividef(S0 - 1.0f, (float)C0);   // seeded step
#pragma unroll 1
        for (int it = 0; it < 32; ++it) {
            float d0 = c0 - T;
            float d1 = c1 - T;
            float s = 0.0f;
            if (d0 > 0.0f) s += d0;
            if (d1 > 0.0f) s += d1;
            int c = __popc(__ballot_sync(0xFFFFFFFFu, d0 > 0.0f))
                  + __popc(__ballot_sync(0xFFFFFFFFu, d1 > 0.0f));
#pragma unroll
            for (int o = 16; o > 0; o >>= 1)
                s += __shfl_xor_sync(0xFFFFFFFFu, s, o);
            // c >= 1 guaranteed: the zmax element is always a candidate and
            // multi-candidate lanes divert to the fallback path.
            float delta = __fdividef(s - 1.0f, (float)c);
            T += delta;
            if (fabsf(delta) < 1e-6f) break;
        }
        tau = T;
    } else {
        // ---- Fallback: proven block-Newton (block-uniform branch) ----
        float T = T0;
#pragma unroll 1
        for (int it = 0; it < 32; ++it) {
            const int b = it & 1;
            float s = 0.0f;
            int   c = 0;
#pragma unroll
            for (int e = 0; e < ELEMS; e++) {
                float d = z[e] - T;
                if (d > 0.0f) { s += d; c += 1; }
            }
#pragma unroll
            for (int o = 16; o > 0; o >>= 1) {
                s += __shfl_xor_sync(0xFFFFFFFFu, s, o);
                c += __shfl_xor_sync(0xFFFFFFFFu, c, o);
            }
            if (lane == 0) { fs[b][wid] = s; fc[b][wid] = c; }
            __syncthreads();
            float S = 0.0f;
            int   C = 0;
#pragma unroll
            for (int i = 0; i < NWARPS; i++) { S += fs[b][i]; C += fc[b][i]; }

            if (C == 0) break;
            float delta = __fdividef(S - 1.0f, (float)C);
            T += delta;
            if (fabsf(delta) < 1e-6f) break;
        }
        tau = T;
    }

    // ---- Output: relu(z - tau). Masked entries are ~-2e7, relu -> 0. ----
#pragma unroll
    for (int v = 0; v < VEC; v++) {
        float4 ov;
        ov.x = fmaxf(0.0f, z[v * 4 + 0] - tau);
        ov.y = fmaxf(0.0f, z[v * 4 + 1] - tau);
        ov.z = fmaxf(0.0f, z[v * 4 + 2] - tau);
        ov.w = fmaxf(0.0f, z[v * 4 + 3] - tau);
        orow[t + v * THREADS] = ov;
    }
}

extern "C" void kernel_launch(void* const* d_in, const int* in_sizes, int n_in,
                              void* d_out, int out_size) {
    const float* x = (const float*)d_in[0];
    const float* m = (const float*)d_in[1];
    float* out = (float*)d_out;
    sparsemax_kernel<<<ROWS, THREADS>>>(x, m, out);
}

// round 17
// speedup vs baseline: 1.0081x; 1.0081x over previous
#include <cuda_runtime.h>
#include <cuda_bf16.h>

// Sparsemax over rows: x, mask are [8192, 4096] fp32; out fp32 same shape.
// z = (mask ? x : NEG_BIG) * 2 ; tau solves sum(relu(z - tau)) = 1 ;
// out = relu(z - tau)  (mask multiply implied: masked z is hugely negative).
//
// FINAL (== R14, best measured wall 62.2 us; dram ~82% == streaming ceiling
// for this 2R:1W compulsory-traffic pattern on GB300, ~95% of the measured
// LTS cap):
//   - front-batched 8x LDG.128 per thread for MLP (latency covered by
//     in-flight loads, not occupancy)
//   - tau >= zmax-1 => support lies in {z > zmax-1} (typically 2-6 elems);
//     deterministic prefix-scan gather to shared (CAP 64, 2 cand regs/lane)
//   - every warp redundantly runs a barrier-free slim Newton: ballot+popc
//     count, 5-shuffle sum, __fdividef step (identical tau in all warps)
//   - proven block-Newton fallback if candidates overflow (block-uniform)

#define ROWS 8192
#define COLS 4096
#define THREADS 256
#define NWARPS (THREADS / 32)
#define ELEMS (COLS / THREADS)   // 16 floats per thread
#define VEC (ELEMS / 4)          // 4 float4 per thread
#define CAP 64                   // candidate buffer (2 per lane)

__global__ __launch_bounds__(THREADS, 5)
void sparsemax_kernel(const float* __restrict__ x,
                      const float* __restrict__ m,
                      float* __restrict__ out) {
    const int row = blockIdx.x;
    const int t   = threadIdx.x;
    const int lane = t & 31;
    const int wid  = t >> 5;

    const float4* __restrict__ xr = reinterpret_cast<const float4*>(x + (size_t)row * COLS);
    const float4* __restrict__ mr = reinterpret_cast<const float4*>(m + (size_t)row * COLS);
    float4* __restrict__ orow     = reinterpret_cast<float4*>(out + (size_t)row * COLS);

    __shared__ float shs[2][NWARPS];   // reduce scratch (max / fallback s)
    __shared__ int   shc[2][NWARPS];   // warp candidate counts / fallback c
    __shared__ float cand[CAP];        // gathered candidates

    // ---- Front-batch ALL loads (8 x LDG.128 in flight per thread) ----
    float4 xv[VEC];
    float4 mv[VEC];
#pragma unroll
    for (int v = 0; v < VEC; v++) xv[v] = xr[t + v * THREADS];
#pragma unroll
    for (int v = 0; v < VEC; v++) mv[v] = mr[t + v * THREADS];

    // ---- Apply mask + temperature, track local max ----
    float z[ELEMS];
    float vmax = -3.0e38f;
    const float NEGZ = -9999999.9f * 2.0f;  // masked value after temperature
#pragma unroll
    for (int v = 0; v < VEC; v++) {
        float z0 = (mv[v].x != 0.0f) ? (xv[v].x * 2.0f) : NEGZ;
        float z1 = (mv[v].y != 0.0f) ? (xv[v].y * 2.0f) : NEGZ;
        float z2 = (mv[v].z != 0.0f) ? (xv[v].z * 2.0f) : NEGZ;
        float z3 = (mv[v].w != 0.0f) ? (xv[v].w * 2.0f) : NEGZ;
        z[v * 4 + 0] = z0;
        z[v * 4 + 1] = z1;
        z[v * 4 + 2] = z2;
        z[v * 4 + 3] = z3;
        vmax = fmaxf(vmax, fmaxf(fmaxf(z0, z1), fmaxf(z2, z3)));
    }

    // ---- Block max reduction ----
#pragma unroll
    for (int o = 16; o > 0; o >>= 1)
        vmax = fmaxf(vmax, __shfl_xor_sync(0xFFFFFFFFu, vmax, o));
    if (lane == 0) shs[0][wid] = vmax;
    __syncthreads();                       // barrier 1
    float zmax = -3.0e38f;
#pragma unroll
    for (int i = 0; i < NWARPS; i++) zmax = fmaxf(zmax, shs[0][i]);

    const float T0 = zmax - 1.0f;

    // ---- Count candidates (z > T0) per thread; deterministic warp scan ----
    int lc = 0;
#pragma unroll
    for (int e = 0; e < ELEMS; e++) lc += (z[e] > T0) ? 1 : 0;

    int inc = lc;                          // inclusive prefix over lanes
#pragma unroll
    for (int o = 1; o < 32; o <<= 1) {
        int v = __shfl_up_sync(0xFFFFFFFFu, inc, o);
        if (lane >= o) inc += v;
    }
    const int excl = inc - lc;
    const int wtot = __shfl_sync(0xFFFFFFFFu, inc, 31);
    if (lane == 31) shc[1][wid] = wtot;
    __syncthreads();                       // barrier 2

    int base = 0, n = 0;
#pragma unroll
    for (int i = 0; i < NWARPS; i++) {
        int w = shc[1][i];
        if (i < wid) base += w;
        n += w;
    }

    float tau;
    if (n <= CAP) {
        // ---- Write candidates at deterministic slots ----
        int off = base + excl;
#pragma unroll
        for (int e = 0; e < ELEMS; e++) {
            if (z[e] > T0) cand[off++] = z[e];
        }
        __syncthreads();                   // barrier 3 (last barrier)

        // ---- Warp-local Newton (every warp redundantly; identical tau) ----
        float c0 = (lane +  0 < n) ? cand[lane +  0] : -3.0e38f;
        float c1 = (lane + 32 < n) ? cand[lane + 32] : -3.0e38f;

        float T = T0;
#pragma unroll 1
        for (int it = 0; it < 32; ++it) {
            float d0 = c0 - T;
            float d1 = c1 - T;
            float s = 0.0f;
            if (d0 > 0.0f) s += d0;
            if (d1 > 0.0f) s += d1;
            // Count via ballots: warp-uniform, no shuffle chain.
            int c = __popc(__ballot_sync(0xFFFFFFFFu, d0 > 0.0f))
                  + __popc(__ballot_sync(0xFFFFFFFFu, d1 > 0.0f));
#pragma unroll
            for (int o = 16; o > 0; o >>= 1)
                s += __shfl_xor_sync(0xFFFFFFFFu, s, o);
            if (c == 0) break;             // degenerate (all-masked row)
            float delta = __fdividef(s - 1.0f, (float)c);
            T += delta;
            if (fabsf(delta) < 1e-6f) break;
        }
        tau = T;
    } else {
        // ---- Fallback: proven block-Newton (block-uniform branch) ----
        __syncthreads();
        float T = T0;
#pragma unroll 1
        for (int it = 0; it < 32; ++it) {
            const int b = (it & 1) ^ 1;
            float s = 0.0f;
            int   c = 0;
#pragma unroll
            for (int e = 0; e < ELEMS; e++) {
                float d = z[e] - T;
                if (d > 0.0f) { s += d; c += 1; }
            }
#pragma unroll
            for (int o = 16; o > 0; o >>= 1) {
                s += __shfl_xor_sync(0xFFFFFFFFu, s, o);
                c += __shfl_xor_sync(0xFFFFFFFFu, c, o);
            }
            if (lane == 0) { shs[b][wid] = s; shc[b][wid] = c; }
            __syncthreads();
            float S = 0.0f;
            int   C = 0;
#pragma unroll
            for (int i = 0; i < NWARPS; i++) { S += shs[b][i]; C += shc[b][i]; }

            if (C == 0) break;
            float delta = __fdividef(S - 1.0f, (float)C);
            T += delta;
            if (fabsf(delta) < 1e-6f) break;
        }
        tau = T;
    }

    // ---- Output: relu(z - tau). Masked entries are ~-2e7, relu -> 0. ----
#pragma unroll
    for (int v = 0; v < VEC; v++) {
        float4 ov;
        ov.x = fmaxf(0.0f, z[v * 4 + 0] - tau);
        ov.y = fmaxf(0.0f, z[v * 4 + 1] - tau);
        ov.z = fmaxf(0.0f, z[v * 4 + 2] - tau);
        ov.w = fmaxf(0.0f, z[v * 4 + 3] - tau);
        orow[t + v * THREADS] = ov;
    }
}

extern "C" void kernel_launch(void* const* d_in, const int* in_sizes, int n_in,
                              void* d_out, int out_size) {
    const float* x = (const float*)d_in[0];
    const float* m = (const float*)d_in[1];
    float* out = (float*)d_out;
    sparsemax_kernel<<<ROWS, THREADS>>>(x, m, out);
}